// round 4
// baseline (speedup 1.0000x reference)
#include <cuda_runtime.h>
#include <cuda_bf16.h>
#include <cstdint>

#define NN 100000
#define EE 1600000
#define DD 128
#define GG 64
#define NPART 296

// ---------------- device scratch ----------------
__device__ float    g_agg[(size_t)NN * DD];     // spmm1 output (fp32)
__device__ unsigned g_xh[(size_t)NN * DD / 2];  // bf16x2 features (layer1 in / layer2 in)
__device__ float    g_w[(size_t)NN * GG];       // per-(src,graph) pooling weights
__device__ float    g_pp[NPART][GG * DD];       // gemm2 partial sums
__device__ uint2    g_gd[NN];                   // packed {gid, ndst}
__device__ int   g_deg_out[NN];
__device__ int   g_deg_in[NN];
__device__ float g_nsrc[NN];
__device__ float g_ndst[NN];
__device__ float g_cnt[GG];
__device__ int   g_off[NN + 1];
__device__ int   g_cursor[NN];
__device__ int   g_sorted[EE];
__device__ int   g_bsum[128];

// ---------------- helpers ----------------
__device__ __forceinline__ unsigned f2tf32(float x) {
    unsigned r;
    asm("cvt.rna.tf32.f32 %0, %1;" : "=r"(r) : "f"(x));
    return r;
}
__device__ __forceinline__ unsigned pack_bf16x2(float lo, float hi) {
    unsigned r;
    asm("cvt.rn.bf16x2.f32 %0, %1, %2;" : "=r"(r) : "f"(hi), "f"(lo));
    return r;
}
__device__ __forceinline__ void mma_tf32(float& d0, float& d1, float& d2, float& d3,
                                         unsigned a0, unsigned a1, unsigned a2, unsigned a3,
                                         unsigned b0, unsigned b1) {
    asm("mma.sync.aligned.m16n8k8.row.col.f32.tf32.tf32.f32 "
        "{%0,%1,%2,%3}, {%4,%5,%6,%7}, {%8,%9}, {%0,%1,%2,%3};"
        : "+f"(d0), "+f"(d1), "+f"(d2), "+f"(d3)
        : "r"(a0), "r"(a1), "r"(a2), "r"(a3), "r"(b0), "r"(b1));
}
__device__ __forceinline__ float bf_lo(unsigned u) { return __uint_as_float(u << 16); }
__device__ __forceinline__ float bf_hi(unsigned u) { return __uint_as_float(u & 0xffff0000u); }
__device__ __forceinline__ void acc_bf16(float4& a, uint2 u) {
    a.x += bf_lo(u.x); a.y += bf_hi(u.x);
    a.z += bf_lo(u.y); a.w += bf_hi(u.y);
}

// ---------------- degree / norm ----------------
__global__ void k_degree(const int* __restrict__ src, const int* __restrict__ dst, int E) {
    int i = blockIdx.x * blockDim.x + threadIdx.x;
    int stride = gridDim.x * blockDim.x;
    for (; i < E; i += stride) {
        atomicAdd(&g_deg_out[src[i]], 1);
        atomicAdd(&g_deg_in[dst[i]], 1);
    }
}

__global__ void k_norm(const int* __restrict__ gid, int N) {
    int i = blockIdx.x * blockDim.x + threadIdx.x;
    if (i < N) {
        float ns = rsqrtf((float)max(g_deg_out[i], 1));
        float nd = rsqrtf((float)max(g_deg_in[i], 1));
        g_nsrc[i] = ns;
        g_ndst[i] = nd;
        int g = gid[i];
        g_gd[i] = make_uint2((unsigned)g, __float_as_uint(nd));
        atomicAdd(&g_cnt[g], 1.f);
    }
}

// ---------------- scan (CSR offsets from deg_in) ----------------
__global__ void k_scan1(int N) {
    __shared__ int s[256];
    int t = threadIdx.x;
    int base = blockIdx.x * 1024 + t * 4;
    int v0 = 0, v1 = 0, v2 = 0, v3 = 0;
    if (base + 0 < N) v0 = g_deg_in[base + 0];
    if (base + 1 < N) v1 = g_deg_in[base + 1];
    if (base + 2 < N) v2 = g_deg_in[base + 2];
    if (base + 3 < N) v3 = g_deg_in[base + 3];
    int tsum = v0 + v1 + v2 + v3;
    s[t] = tsum;
    __syncthreads();
    for (int o = 1; o < 256; o <<= 1) {
        int x = (t >= o) ? s[t - o] : 0;
        __syncthreads();
        s[t] += x;
        __syncthreads();
    }
    int incl = s[t];
    int excl = incl - tsum;
    if (base + 0 < N) g_off[base + 0] = excl;
    if (base + 1 < N) g_off[base + 1] = excl + v0;
    if (base + 2 < N) g_off[base + 2] = excl + v0 + v1;
    if (base + 3 < N) g_off[base + 3] = excl + v0 + v1 + v2;
    if (t == 255) g_bsum[blockIdx.x] = incl;
}

__global__ void k_scan2(int B) {
    __shared__ int s[128];
    int t = threadIdx.x;
    int v = (t < B) ? g_bsum[t] : 0;
    s[t] = v;
    __syncthreads();
    for (int o = 1; o < 128; o <<= 1) {
        int x = (t >= o) ? s[t - o] : 0;
        __syncthreads();
        s[t] += x;
        __syncthreads();
    }
    if (t < B) g_bsum[t] = s[t] - v;
}

__global__ void k_scan3(int N, int E) {
    int i = blockIdx.x * blockDim.x + threadIdx.x;
    if (i < N) {
        int o = g_off[i] + g_bsum[i >> 10];
        g_off[i] = o;
        g_cursor[i] = o;
    }
    if (i == 0) g_off[N] = E;
}

__global__ void k_scatter(const int* __restrict__ src, const int* __restrict__ dst, int E) {
    int i = blockIdx.x * blockDim.x + threadIdx.x;
    if (i < E) {
        int d = dst[i];
        int p = atomicAdd(&g_cursor[d], 1);
        g_sorted[p] = src[i];
    }
}

// ---------------- w build: w[src][gid[dst]] += ndst[dst] ----------------
__global__ void k_wbuild(const int* __restrict__ src, const int* __restrict__ dst, int E) {
    int i = blockIdx.x * blockDim.x + threadIdx.x;
    int stride = gridDim.x * blockDim.x;
    for (; i < E; i += stride) {
        int s = src[i];
        uint2 gd = g_gd[dst[i]];
        atomicAdd(&g_w[(size_t)s * GG + gd.x], __uint_as_float(gd.y));
    }
}

// ---------------- prep: g_xh = bf16(in_feat * nsrc) ----------------
__global__ void k_prep(const float* __restrict__ x, int N) {
    int i = blockIdx.x * blockDim.x + threadIdx.x;
    if (i >= N * 32) return;
    int n = i >> 5;
    float s = g_nsrc[n];
    float4 v = ((const float4*)x)[i];
    uint2 u;
    u.x = pack_bf16x2(v.x * s, v.y * s);
    u.y = pack_bf16x2(v.z * s, v.w * s);
    ((uint2*)g_xh)[i] = u;
}

// ---------------- SpMM layer 1: warp per node, shuffle-broadcast indices, MLP 8 ----------------
__global__ void __launch_bounds__(256) k_spmm1(int N) {
    int warp = (blockIdx.x * blockDim.x + threadIdx.x) >> 5;
    if (warp >= N) return;
    int lane = threadIdx.x & 31;
    const uint2* xh = (const uint2*)g_xh;
    int e0 = g_off[warp];
    int e1 = g_off[warp + 1];
    float4 acc = make_float4(0.f, 0.f, 0.f, 0.f);
    for (int base = e0; base < e1; base += 32) {
        int nrem = e1 - base;
        int idx = (lane < nrem) ? g_sorted[base + lane] : 0;
        int m = min(32, nrem);
        int j = 0;
        for (; j + 8 <= m; j += 8) {
            uint2 u[8];
#pragma unroll
            for (int q = 0; q < 8; q++) {
                int s = __shfl_sync(0xffffffffu, idx, j + q);
                u[q] = xh[(size_t)s * 32 + lane];
            }
#pragma unroll
            for (int q = 0; q < 8; q++) acc_bf16(acc, u[q]);
        }
        for (; j < m; j++) {
            int s = __shfl_sync(0xffffffffu, idx, j);
            acc_bf16(acc, xh[(size_t)s * 32 + lane]);
        }
    }
    *(float4*)(g_agg + (size_t)warp * DD + lane * 4) = acc;
}

// ---------------- fused dense stage 1 (tf32 tensor cores) ----------------
#define SA_STRIDE 136
#define SW_STRIDE 136
__global__ void __launch_bounds__(256) k_gemm1(const float* __restrict__ W,
                                               const float* __restrict__ b, int N) {
    extern __shared__ float smem[];
    float* sA = smem;
    float* sW = smem + 64 * SA_STRIDE;

    int t = threadIdx.x;
    int row0 = blockIdx.x * 64;
    int wid = t >> 5;
    int lane = t & 31;
    int g = lane >> 2;
    int tg = lane & 3;
    int wm = wid >> 2;
    int wn = wid & 3;

#pragma unroll
    for (int i = 0; i < 16; i++) {
        int f = t + i * 256;
        int r = f >> 5;
        int c = f & 31;
        float4 v = *(const float4*)(W + r * 128 + c * 4);
        *(float4*)(sW + r * SW_STRIDE + c * 4) = v;
    }
#pragma unroll
    for (int i = 0; i < 8; i++) {
        int f = t + i * 256;
        int r = f >> 5;
        int c = f & 31;
        int row = row0 + r;
        float4 v = make_float4(0.f, 0.f, 0.f, 0.f);
        if (row < N) {
            v = *(const float4*)(g_agg + (size_t)row * DD + c * 4);
            float s = g_ndst[row];
            v.x *= s; v.y *= s; v.z *= s; v.w *= s;
        }
        *(float4*)(sA + r * SA_STRIDE + c * 4) = v;
    }
    __syncthreads();

    float acc[2][4][4];
#pragma unroll
    for (int i = 0; i < 2; i++)
#pragma unroll
        for (int j = 0; j < 4; j++)
#pragma unroll
            for (int q = 0; q < 4; q++) acc[i][j][q] = 0.f;

    const float* pA = sA + (wm * 32 + g) * SA_STRIDE + tg;
    const float* pB = sW + tg * SW_STRIDE + wn * 32 + g;

#pragma unroll
    for (int ks = 0; ks < 16; ks++) {
        int k0 = ks * 8;
        unsigned a[2][4];
#pragma unroll
        for (int i = 0; i < 2; i++) {
            const float* p = pA + i * 16 * SA_STRIDE + k0;
            a[i][0] = f2tf32(p[0]);
            a[i][1] = f2tf32(p[8 * SA_STRIDE]);
            a[i][2] = f2tf32(p[4]);
            a[i][3] = f2tf32(p[8 * SA_STRIDE + 4]);
        }
        unsigned bb[4][2];
#pragma unroll
        for (int j = 0; j < 4; j++) {
            const float* p = pB + k0 * SW_STRIDE + j * 8;
            bb[j][0] = f2tf32(p[0]);
            bb[j][1] = f2tf32(p[4 * SW_STRIDE]);
        }
#pragma unroll
        for (int i = 0; i < 2; i++)
#pragma unroll
            for (int j = 0; j < 4; j++)
                mma_tf32(acc[i][j][0], acc[i][j][1], acc[i][j][2], acc[i][j][3],
                         a[i][0], a[i][1], a[i][2], a[i][3], bb[j][0], bb[j][1]);
    }

#pragma unroll
    for (int i = 0; i < 2; i++) {
        int rA = row0 + wm * 32 + i * 16 + g;
        int rB = rA + 8;
        float sA_ = (rA < N) ? g_nsrc[rA] : 0.f;
        float sB_ = (rB < N) ? g_nsrc[rB] : 0.f;
#pragma unroll
        for (int j = 0; j < 4; j++) {
            int c = wn * 32 + j * 8 + tg * 2;
            float bx = b[c], by = b[c + 1];
            if (rA < N) {
                float x0 = fmaxf(acc[i][j][0] + bx, 0.f) * sA_;
                float x1 = fmaxf(acc[i][j][1] + by, 0.f) * sA_;
                g_xh[(size_t)rA * 64 + (c >> 1)] = pack_bf16x2(x0, x1);
            }
            if (rB < N) {
                float x2 = fmaxf(acc[i][j][2] + bx, 0.f) * sB_;
                float x3 = fmaxf(acc[i][j][3] + by, 0.f) * sB_;
                g_xh[(size_t)rB * 64 + (c >> 1)] = pack_bf16x2(x2, x3);
            }
        }
    }
}

// ---------------- gemm2: pool_part[b] = w_chunk^T @ xh_chunk  (64 x 128) ----------------
__global__ void __launch_bounds__(256) k_gemm2(int N) {
    __shared__ unsigned sxh[8 * 64];
    __shared__ float sw[8 * 64];
    int t = threadIdx.x;
    int chunk = (N + NPART - 1) / NPART;
    int nb0 = blockIdx.x * chunk;
    int nend = min(nb0 + chunk, N);

    int dgrp = t & 31;   // owns d = dgrp*4 .. +4  (pairs dgrp*2, dgrp*2+1)
    int ggrp = t >> 5;   // owns g = ggrp*8 .. +8

    float acc[8][4];
#pragma unroll
    for (int j = 0; j < 8; j++)
#pragma unroll
        for (int q = 0; q < 4; q++) acc[j][q] = 0.f;

    for (int nb = nb0; nb < nend; nb += 8) {
#pragma unroll
        for (int i = 0; i < 2; i++) {
            int word = t + i * 256;          // 0..511
            int s = word >> 6, p = word & 63;
            int n = nb + s;
            sxh[word] = (n < nend) ? g_xh[(size_t)n * 64 + p] : 0u;
        }
#pragma unroll
        for (int i = 0; i < 2; i++) {
            int word = t + i * 256;
            int s = word >> 6, gg = word & 63;
            int n = nb + s;
            sw[word] = (n < nend) ? g_w[(size_t)n * 64 + gg] : 0.f;
        }
        __syncthreads();
#pragma unroll
        for (int s = 0; s < 8; s++) {
            uint2 xp = *(uint2*)&sxh[s * 64 + dgrp * 2];
            float x0 = bf_lo(xp.x), x1 = bf_hi(xp.x);
            float x2 = bf_lo(xp.y), x3 = bf_hi(xp.y);
#pragma unroll
            for (int j = 0; j < 8; j++) {
                float wv = sw[s * 64 + ggrp * 8 + j];
                acc[j][0] += wv * x0;
                acc[j][1] += wv * x1;
                acc[j][2] += wv * x2;
                acc[j][3] += wv * x3;
            }
        }
        __syncthreads();
    }

    float* pp = g_pp[blockIdx.x];
#pragma unroll
    for (int j = 0; j < 8; j++)
#pragma unroll
        for (int q = 0; q < 4; q++)
            pp[(ggrp * 8 + j) * DD + dgrp * 4 + q] = acc[j][q];
}

// ---------------- final: out = (Σ_p pp / cnt) @ W2 + b2 ----------------
__global__ void k_final(const float* __restrict__ W2, const float* __restrict__ b2,
                        float* __restrict__ out) {
    __shared__ float srow[DD];
    int g = blockIdx.x, t = threadIdx.x;
    float s = 0.f;
#pragma unroll 4
    for (int p = 0; p < NPART; p++) s += g_pp[p][g * DD + t];
    srow[t] = s / fmaxf(g_cnt[g], 1.f);
    __syncthreads();
    float a = b2[t];
#pragma unroll 8
    for (int k = 0; k < DD; k++) a += srow[k] * W2[k * DD + t];
    out[g * DD + t] = a;
}

// ---------------- launch ----------------
extern "C" void kernel_launch(void* const* d_in, const int* in_sizes, int n_in,
                              void* d_out, int out_size) {
    const float* in_feat = (const float*)d_in[0];
    const float* W1 = (const float*)d_in[1];
    const float* b1 = (const float*)d_in[2];
    const float* W2 = (const float*)d_in[3];
    const float* b2 = (const float*)d_in[4];
    const int* src = (const int*)d_in[5];
    const int* dst = (const int*)d_in[6];
    const int* gid = (const int*)d_in[7];
    int N = in_sizes[0] / DD;
    int E = in_sizes[5];
    (void)n_in; (void)out_size;

    void *p_do, *p_di, *p_cnt, *p_w;
    cudaGetSymbolAddress(&p_do, g_deg_out);
    cudaGetSymbolAddress(&p_di, g_deg_in);
    cudaGetSymbolAddress(&p_cnt, g_cnt);
    cudaGetSymbolAddress(&p_w, g_w);

    const int gemm_smem = (64 * SA_STRIDE + 128 * SW_STRIDE) * (int)sizeof(float);
    static int smem_set = 0;
    if (!smem_set) {
        cudaFuncSetAttribute(k_gemm1, cudaFuncAttributeMaxDynamicSharedMemorySize, gemm_smem);
        smem_set = 1;
    }

    cudaMemsetAsync(p_do, 0, N * sizeof(int));
    cudaMemsetAsync(p_di, 0, N * sizeof(int));
    cudaMemsetAsync(p_cnt, 0, GG * sizeof(float));
    cudaMemsetAsync(p_w, 0, (size_t)N * GG * sizeof(float));

    k_degree<<<1024, 256>>>(src, dst, E);
    k_norm<<<(N + 255) / 256, 256>>>(gid, N);

    int B = (N + 1023) / 1024;
    k_scan1<<<B, 256>>>(N);
    k_scan2<<<1, 128>>>(B);
    k_scan3<<<(N + 255) / 256, 256>>>(N, E);
    k_scatter<<<(E + 255) / 256, 256>>>(src, dst, E);
    k_wbuild<<<1024, 256>>>(src, dst, E);

    k_prep<<<(N * 32 + 255) / 256, 256>>>(in_feat, N);
    k_spmm1<<<(N + 7) / 8, 256>>>(N);
    k_gemm1<<<(N + 63) / 64, 256, gemm_smem>>>(W1, b1, N);
    k_gemm2<<<NPART, 256>>>(N);
    k_final<<<GG, DD>>>(W2, b2, (float*)d_out);
}

// round 5
// speedup vs baseline: 1.0561x; 1.0561x over previous
#include <cuda_runtime.h>
#include <cuda_bf16.h>
#include <cstdint>

#define NN 100000
#define EE 1600000
#define DD 128
#define GG 64
#define NPART 296

// ---------------- device scratch ----------------
__device__ float    g_agg[(size_t)NN * DD];     // spmm1 output (fp32)
__device__ unsigned g_xh[(size_t)NN * DD / 2];  // bf16x2 features (layer1 in / layer2 in)
__device__ float    g_w[(size_t)NN * GG];       // per-(src,graph) pooling weights
__device__ float    g_pp[NPART][GG * DD];       // gemm2 partial sums
__device__ uint2    g_gd[NN];                   // packed {gid, ndst}
__device__ int      g_deg[2 * NN];              // [0,NN)=deg_out, [NN,2NN)=deg_in
__device__ float    g_nsrc[NN];
__device__ float    g_ndst[NN];
__device__ float    g_cnt[GG];
__device__ int      g_off[NN];
__device__ int      g_cursor[NN];
__device__ int      g_sorted[EE];
__device__ int      g_counter;

// ---------------- helpers ----------------
__device__ __forceinline__ unsigned f2tf32(float x) {
    unsigned r;
    asm("cvt.rna.tf32.f32 %0, %1;" : "=r"(r) : "f"(x));
    return r;
}
__device__ __forceinline__ unsigned pack_bf16x2(float lo, float hi) {
    unsigned r;
    asm("cvt.rn.bf16x2.f32 %0, %1, %2;" : "=r"(r) : "f"(hi), "f"(lo));
    return r;
}
__device__ __forceinline__ void mma_tf32(float& d0, float& d1, float& d2, float& d3,
                                         unsigned a0, unsigned a1, unsigned a2, unsigned a3,
                                         unsigned b0, unsigned b1) {
    asm("mma.sync.aligned.m16n8k8.row.col.f32.tf32.tf32.f32 "
        "{%0,%1,%2,%3}, {%4,%5,%6,%7}, {%8,%9}, {%0,%1,%2,%3};"
        : "+f"(d0), "+f"(d1), "+f"(d2), "+f"(d3)
        : "r"(a0), "r"(a1), "r"(a2), "r"(a3), "r"(b0), "r"(b1));
}
__device__ __forceinline__ float bf_lo(unsigned u) { return __uint_as_float(u << 16); }
__device__ __forceinline__ float bf_hi(unsigned u) { return __uint_as_float(u & 0xffff0000u); }
__device__ __forceinline__ void acc_bf16(float4& a, uint2 u) {
    a.x += bf_lo(u.x); a.y += bf_hi(u.x);
    a.z += bf_lo(u.y); a.w += bf_hi(u.y);
}

// ---------------- kernel 0: degree count + zero w/cnt/counter ----------------
__global__ void k_degree(const int* __restrict__ src, const int* __restrict__ dst, int E) {
    int i0 = blockIdx.x * blockDim.x + threadIdx.x;
    int stride = gridDim.x * blockDim.x;
    // zero g_w (used two kernels later), g_cnt, g_counter
    float4 z = make_float4(0.f, 0.f, 0.f, 0.f);
    for (int i = i0; i < NN * GG / 4; i += stride) ((float4*)g_w)[i] = z;
    if (i0 < GG) g_cnt[i0] = 0.f;
    if (i0 == GG) g_counter = 0;
    for (int i = i0; i < E; i += stride) {
        atomicAdd(&g_deg[src[i]], 1);
        atomicAdd(&g_deg[NN + dst[i]], 1);
    }
}

// ---------------- kernel 1: norms, gd pack, graph counts, segment offsets ----------------
__global__ void k_nodeprep(const int* __restrict__ gid, int N) {
    int i = blockIdx.x * blockDim.x + threadIdx.x;
    if (i < N) {
        int dout = g_deg[i];
        int din = g_deg[NN + i];
        float ns = rsqrtf((float)max(dout, 1));
        float nd = rsqrtf((float)max(din, 1));
        g_nsrc[i] = ns;
        g_ndst[i] = nd;
        int g = gid[i];
        g_gd[i] = make_uint2((unsigned)g, __float_as_uint(nd));
        atomicAdd(&g_cnt[g], 1.f);
        int off = atomicAdd(&g_counter, din);   // arbitrary-order segment assignment
        g_off[i] = off;
        g_cursor[i] = off;
    }
}

// ---------------- kernel 2: scatter + wbuild (edges) and bf16 prep (nodes) ----------------
__global__ void k_edge_node(const int* __restrict__ src, const int* __restrict__ dst,
                            const float* __restrict__ x, int E, int N) {
    int i = blockIdx.x * blockDim.x + threadIdx.x;
    if (i < E) {
        int s = src[i];
        int d = dst[i];
        int p = atomicAdd(&g_cursor[d], 1);
        g_sorted[p] = s;
        uint2 gd = g_gd[d];
        atomicAdd(&g_w[(size_t)s * GG + gd.x], __uint_as_float(gd.y));
    } else {
        int j = i - E;                       // float4 index over node features
        if (j < N * 32) {
            int n = j >> 5;
            float sc = g_nsrc[n];
            float4 v = ((const float4*)x)[j];
            uint2 u;
            u.x = pack_bf16x2(v.x * sc, v.y * sc);
            u.y = pack_bf16x2(v.z * sc, v.w * sc);
            ((uint2*)g_xh)[j] = u;
        }
    }
}

// ---------------- kernel 3 (PROFILED SLOT): SpMM layer 1 ----------------
__global__ void __launch_bounds__(256) k_spmm1(int N) {
    int warp = (blockIdx.x * blockDim.x + threadIdx.x) >> 5;
    if (warp >= N) return;
    int lane = threadIdx.x & 31;
    const uint2* xh = (const uint2*)g_xh;
    int e0 = g_off[warp];
    int e1 = e0 + g_deg[NN + warp];
    float4 acc = make_float4(0.f, 0.f, 0.f, 0.f);
    for (int base = e0; base < e1; base += 32) {
        int nrem = e1 - base;
        int idx = (lane < nrem) ? g_sorted[base + lane] : 0;
        int m = min(32, nrem);
        int j = 0;
        for (; j + 8 <= m; j += 8) {
            uint2 u[8];
#pragma unroll
            for (int q = 0; q < 8; q++) {
                int s = __shfl_sync(0xffffffffu, idx, j + q);
                u[q] = xh[(size_t)s * 32 + lane];
            }
#pragma unroll
            for (int q = 0; q < 8; q++) acc_bf16(acc, u[q]);
        }
        for (; j < m; j++) {
            int s = __shfl_sync(0xffffffffu, idx, j);
            acc_bf16(acc, xh[(size_t)s * 32 + lane]);
        }
    }
    *(float4*)(g_agg + (size_t)warp * DD + lane * 4) = acc;
}

// ---------------- fused dense stage 1 (tf32 tensor cores) ----------------
#define SA_STRIDE 136
#define SW_STRIDE 136
__global__ void __launch_bounds__(256) k_gemm1(const float* __restrict__ W,
                                               const float* __restrict__ b, int N) {
    extern __shared__ float smem[];
    float* sA = smem;
    float* sW = smem + 64 * SA_STRIDE;

    int t = threadIdx.x;
    int row0 = blockIdx.x * 64;
    int wid = t >> 5;
    int lane = t & 31;
    int g = lane >> 2;
    int tg = lane & 3;
    int wm = wid >> 2;
    int wn = wid & 3;

#pragma unroll
    for (int i = 0; i < 16; i++) {
        int f = t + i * 256;
        int r = f >> 5;
        int c = f & 31;
        float4 v = *(const float4*)(W + r * 128 + c * 4);
        *(float4*)(sW + r * SW_STRIDE + c * 4) = v;
    }
#pragma unroll
    for (int i = 0; i < 8; i++) {
        int f = t + i * 256;
        int r = f >> 5;
        int c = f & 31;
        int row = row0 + r;
        float4 v = make_float4(0.f, 0.f, 0.f, 0.f);
        if (row < N) {
            v = *(const float4*)(g_agg + (size_t)row * DD + c * 4);
            float s = g_ndst[row];
            v.x *= s; v.y *= s; v.z *= s; v.w *= s;
        }
        *(float4*)(sA + r * SA_STRIDE + c * 4) = v;
    }
    __syncthreads();

    float acc[2][4][4];
#pragma unroll
    for (int i = 0; i < 2; i++)
#pragma unroll
        for (int j = 0; j < 4; j++)
#pragma unroll
            for (int q = 0; q < 4; q++) acc[i][j][q] = 0.f;

    const float* pA = sA + (wm * 32 + g) * SA_STRIDE + tg;
    const float* pB = sW + tg * SW_STRIDE + wn * 32 + g;

#pragma unroll
    for (int ks = 0; ks < 16; ks++) {
        int k0 = ks * 8;
        unsigned a[2][4];
#pragma unroll
        for (int i = 0; i < 2; i++) {
            const float* p = pA + i * 16 * SA_STRIDE + k0;
            a[i][0] = f2tf32(p[0]);
            a[i][1] = f2tf32(p[8 * SA_STRIDE]);
            a[i][2] = f2tf32(p[4]);
            a[i][3] = f2tf32(p[8 * SA_STRIDE + 4]);
        }
        unsigned bb[4][2];
#pragma unroll
        for (int j = 0; j < 4; j++) {
            const float* p = pB + k0 * SW_STRIDE + j * 8;
            bb[j][0] = f2tf32(p[0]);
            bb[j][1] = f2tf32(p[4 * SW_STRIDE]);
        }
#pragma unroll
        for (int i = 0; i < 2; i++)
#pragma unroll
            for (int j = 0; j < 4; j++)
                mma_tf32(acc[i][j][0], acc[i][j][1], acc[i][j][2], acc[i][j][3],
                         a[i][0], a[i][1], a[i][2], a[i][3], bb[j][0], bb[j][1]);
    }

#pragma unroll
    for (int i = 0; i < 2; i++) {
        int rA = row0 + wm * 32 + i * 16 + g;
        int rB = rA + 8;
        float sA_ = (rA < N) ? g_nsrc[rA] : 0.f;
        float sB_ = (rB < N) ? g_nsrc[rB] : 0.f;
#pragma unroll
        for (int j = 0; j < 4; j++) {
            int c = wn * 32 + j * 8 + tg * 2;
            float bx = b[c], by = b[c + 1];
            if (rA < N) {
                float x0 = fmaxf(acc[i][j][0] + bx, 0.f) * sA_;
                float x1 = fmaxf(acc[i][j][1] + by, 0.f) * sA_;
                g_xh[(size_t)rA * 64 + (c >> 1)] = pack_bf16x2(x0, x1);
            }
            if (rB < N) {
                float x2 = fmaxf(acc[i][j][2] + bx, 0.f) * sB_;
                float x3 = fmaxf(acc[i][j][3] + by, 0.f) * sB_;
                g_xh[(size_t)rB * 64 + (c >> 1)] = pack_bf16x2(x2, x3);
            }
        }
    }
}

// ---------------- gemm2: pool partials = w_chunk^T @ xh_chunk ----------------
__global__ void __launch_bounds__(256) k_gemm2(int N) {
    __shared__ unsigned sxh[8 * 64];
    __shared__ float sw[8 * 64];
    int t = threadIdx.x;
    int chunk = (N + NPART - 1) / NPART;
    int nb0 = blockIdx.x * chunk;
    int nend = min(nb0 + chunk, N);

    int dgrp = t & 31;
    int ggrp = t >> 5;

    float acc[8][4];
#pragma unroll
    for (int j = 0; j < 8; j++)
#pragma unroll
        for (int q = 0; q < 4; q++) acc[j][q] = 0.f;

    for (int nb = nb0; nb < nend; nb += 8) {
#pragma unroll
        for (int i = 0; i < 2; i++) {
            int word = t + i * 256;
            int s = word >> 6, p = word & 63;
            int n = nb + s;
            sxh[word] = (n < nend) ? g_xh[(size_t)n * 64 + p] : 0u;
        }
#pragma unroll
        for (int i = 0; i < 2; i++) {
            int word = t + i * 256;
            int s = word >> 6, gg = word & 63;
            int n = nb + s;
            sw[word] = (n < nend) ? g_w[(size_t)n * 64 + gg] : 0.f;
        }
        __syncthreads();
#pragma unroll
        for (int s = 0; s < 8; s++) {
            uint2 xp = *(uint2*)&sxh[s * 64 + dgrp * 2];
            float x0 = bf_lo(xp.x), x1 = bf_hi(xp.x);
            float x2 = bf_lo(xp.y), x3 = bf_hi(xp.y);
#pragma unroll
            for (int j = 0; j < 8; j++) {
                float wv = sw[s * 64 + ggrp * 8 + j];
                acc[j][0] += wv * x0;
                acc[j][1] += wv * x1;
                acc[j][2] += wv * x2;
                acc[j][3] += wv * x3;
            }
        }
        __syncthreads();
    }

    float* pp = g_pp[blockIdx.x];
#pragma unroll
    for (int j = 0; j < 8; j++)
#pragma unroll
        for (int q = 0; q < 4; q++)
            pp[(ggrp * 8 + j) * DD + dgrp * 4 + q] = acc[j][q];
}

// ---------------- final: out = (Σ_p pp / cnt) @ W2 + b2 ----------------
__global__ void k_final(const float* __restrict__ W2, const float* __restrict__ b2,
                        float* __restrict__ out) {
    __shared__ float srow[DD];
    int g = blockIdx.x, t = threadIdx.x;
    float s = 0.f;
#pragma unroll 4
    for (int p = 0; p < NPART; p++) s += g_pp[p][g * DD + t];
    srow[t] = s / fmaxf(g_cnt[g], 1.f);
    __syncthreads();
    float a = b2[t];
#pragma unroll 8
    for (int k = 0; k < DD; k++) a += srow[k] * W2[k * DD + t];
    out[g * DD + t] = a;
}

// ---------------- launch ----------------
extern "C" void kernel_launch(void* const* d_in, const int* in_sizes, int n_in,
                              void* d_out, int out_size) {
    const float* in_feat = (const float*)d_in[0];
    const float* W1 = (const float*)d_in[1];
    const float* b1 = (const float*)d_in[2];
    const float* W2 = (const float*)d_in[3];
    const float* b2 = (const float*)d_in[4];
    const int* src = (const int*)d_in[5];
    const int* dst = (const int*)d_in[6];
    const int* gid = (const int*)d_in[7];
    int N = in_sizes[0] / DD;
    int E = in_sizes[5];
    (void)n_in; (void)out_size;

    void* p_deg;
    cudaGetSymbolAddress(&p_deg, g_deg);

    const int gemm_smem = (64 * SA_STRIDE + 128 * SW_STRIDE) * (int)sizeof(float);
    static int smem_set = 0;
    if (!smem_set) {
        cudaFuncSetAttribute(k_gemm1, cudaFuncAttributeMaxDynamicSharedMemorySize, gemm_smem);
        smem_set = 1;
    }

    cudaMemsetAsync(p_deg, 0, 2 * NN * sizeof(int));

    k_degree<<<1024, 256>>>(src, dst, E);                       // kernel 0
    k_nodeprep<<<(N + 255) / 256, 256>>>(gid, N);               // kernel 1
    k_edge_node<<<(E + N * 32 + 255) / 256, 256>>>(src, dst, in_feat, E, N); // kernel 2
    k_spmm1<<<(N + 7) / 8, 256>>>(N);                           // kernel 3 <- profiled
    k_gemm1<<<(N + 63) / 64, 256, gemm_smem>>>(W1, b1, N);      // kernel 4
    k_gemm2<<<NPART, 256>>>(N);                                 // kernel 5
    k_final<<<GG, DD>>>(W2, b2, (float*)d_out);                 // kernel 6
}